// round 7
// baseline (speedup 1.0000x reference)
#include <cuda_runtime.h>
#include <math.h>
#include <stdint.h>

#define DIM    240
#define SEQ    1024
#define NB     240
#define NROW   (NB*SEQ)      // 245760
#define MTILE  128
#define NTILES (NROW/MTILE)  // 1920
#define KC     32
#define NCHUNK 8
#define THREADS 256
#define PGRID  152

#define A_CH_BYTES  16384u   // 128 rows x 128B
#define B_CH_BYTES  30720u   // 240 rows x 128B
#define W_BYTES     (NCHUNK*B_CH_BYTES)   // 245760... no: 8*30720 = 245760? -> 245760 bytes? (see note: actual 8*30720=245760) 
// NOTE: weights stored as NCHUNK chunks of B_CH_BYTES = 8*30720 = 245760 bytes?? -> 240KB each. WRONG for residency.
// Correction: B operand per chunk covers K=32 of 240 -> full weight = 240x240 tf32 = 230400B logical,
// padded chunk layout = 8 * 30720 = 245760B. Too big for 3 resident. We keep K-chunked images but
// only 61440B per weight?  -> Actually 30720B per chunk covers 240 rows x 32 k x 4B = 30720B. Full = 245760B.
// Residency of 3 full weights = 737KB: impossible. INSTEAD: weights stay chunk-streamed, but we
// cache them in L2 (small) — the residency plan applies to MT/diag only? No — see code: we keep
// double-buffered weight streaming but persistent CTAs still help A/Xc and remove launch waves.
// FINAL LAYOUT (streaming, as R6) with persistent loop + TS-mode GEMM2 (Y in TMEM, no Y smem).

#define XC_BYTES    122880u  // 128 x 240 x 4

// idesc: dtype=f32(1<<4), atype=tf32(2<<7), btype=tf32(2<<10), N=240(30<<17), M=128(8<<24)
#define IDESC ((1u<<4)|(2u<<7)|(2u<<10)|(30u<<17)|(8u<<24))

#if !defined(__CUDA_ARCH__) || defined(__CUDA_ARCH_FEAT_SM103_ALL) || defined(__CUDA_ARCH_FEAT_SM100_ALL) || defined(__CUDA_ARCH_FEAT_SM101_ALL)
#define HAS_TC 1
#else
#define HAS_TC 0
#endif

// ---------------- device scratch ----------------
__device__ __align__(1024) float g_Wsw[3][NCHUNK*7680];   // Wx,Wg,Wo swizzled tf32 chunks
__device__ __align__(1024) float g_MTsw[NCHUNK*7680];     // MT swizzled tf32 chunks
__device__ __align__(1024) float g_xsw[(size_t)NROW*256]; // x tiles swizzled tf32
__device__ __align__(1024) float g_Xc [(size_t)NROW*DIM]; // cumsum of x over s
__device__ __align__(1024) float g_diagT[SEQ*DIM];        // diagT[s*240 + b]

// ---------------- helpers ----------------
__device__ __forceinline__ uint32_t smem_u32(const void* p){
    uint32_t a;
    asm("{ .reg .u64 t; cvta.to.shared.u64 t, %1; cvt.u32.u64 %0, t; }" : "=r"(a) : "l"(p));
    return a;
}
__device__ __forceinline__ float sigf(float v){
    float t = -1.4426950408889634f * v;
    float e; asm("ex2.approx.f32 %0, %1;" : "=f"(e) : "f"(t));
    float r; asm("rcp.approx.f32 %0, %1;" : "=f"(r) : "f"(1.f + e));
    return r;
}
__device__ __forceinline__ uint32_t cvt_tf32(float v){
    uint32_t r; asm("cvt.rna.tf32.f32 %0, %1;" : "=r"(r) : "f"(v)); return r;
}
__device__ __forceinline__ uint32_t swz(uint32_t off){ return off ^ ((off >> 3) & 0x70); }
__device__ __forceinline__ uint32_t loc_off(int r, int kl){
    return swz(((uint32_t)(r >> 3) << 10) + ((uint32_t)(r & 7) << 7) + ((uint32_t)kl << 2));
}

#if HAS_TC
__device__ __forceinline__ uint32_t elect_one(){
    uint32_t p;
    asm volatile("{ .reg .pred p; elect.sync _|p, 0xFFFFFFFF; selp.b32 %0, 1, 0, p; }" : "=r"(p));
    return p;
}
__device__ __forceinline__ uint64_t sdesc(uint32_t addr){
    return ((uint64_t)2 << 61) | ((uint64_t)1 << 46) | ((uint64_t)64 << 32)
         | ((uint64_t)1 << 16) | ((uint64_t)(addr >> 4) & 0x3FFF);
}
__device__ __forceinline__ void mma_tf32(uint32_t d, uint64_t a, uint64_t b, uint32_t id, uint32_t en){
    asm volatile(
        "{\n\t.reg .pred p;\n\tsetp.ne.u32 p, %5, 0;\n\t"
        "tcgen05.mma.cta_group::1.kind::tf32 [%0], %1, %2, %3, {%4, %4, %4, %4}, p;\n\t}"
        :: "r"(d), "l"(a), "l"(b), "r"(id), "r"(0u), "r"(en) : "memory");
}
// TS form: A in TMEM
__device__ __forceinline__ void mma_tf32_ts(uint32_t d, uint32_t a, uint64_t b, uint32_t id, uint32_t en){
    asm volatile(
        "{\n\t.reg .pred p;\n\tsetp.ne.u32 p, %5, 0;\n\t"
        "tcgen05.mma.cta_group::1.kind::tf32 [%0], [%1], %2, %3, {%4, %4, %4, %4}, p;\n\t}"
        :: "r"(d), "r"(a), "l"(b), "r"(id), "r"(0u), "r"(en) : "memory");
}
__device__ __forceinline__ void mbar_wait(uint32_t mbar, uint32_t phase){
    asm volatile(
        "{\n\t.reg .pred P;\n\t"
        "W%=:\n\t"
        "mbarrier.try_wait.parity.acquire.cta.shared::cta.b64 P, [%0], %1, 0x989680;\n\t"
        "@P bra.uni D%=;\n\t"
        "bra.uni W%=;\n\t"
        "D%=:\n\t}"
        :: "r"(mbar), "r"(phase) : "memory");
}
#define TC_ALLOC(sa, n)  asm volatile("tcgen05.alloc.cta_group::1.sync.aligned.shared::cta.b32 [%0], %1;" :: "r"(sa), "r"(n) : "memory")
#define TC_RELINQ()      asm volatile("tcgen05.relinquish_alloc_permit.cta_group::1.sync.aligned;")
#define TC_DEALLOC(t, n) asm volatile("tcgen05.dealloc.cta_group::1.sync.aligned.b32 %0, %1;" :: "r"(t), "r"(n))
#define TC_COMMIT(mb)    asm volatile("tcgen05.commit.cta_group::1.mbarrier::arrive::one.shared::cluster.b64 [%0];" :: "r"(mb) : "memory")
#define TC_WAIT_LD()     asm volatile("tcgen05.wait::ld.sync.aligned;" ::: "memory")
#define TC_WAIT_ST()     asm volatile("tcgen05.wait::st.sync.aligned;" ::: "memory")
#define TC_FENCE_AFTER()  asm volatile("tcgen05.fence::after_thread_sync;" ::: "memory")
#define TC_FENCE_BEFORE() asm volatile("tcgen05.fence::before_thread_sync;" ::: "memory")
#define FENCE_ASYNC()    asm volatile("fence.proxy.async.shared::cta;" ::: "memory")
#define MBAR_INIT(a)     asm volatile("mbarrier.init.shared.b64 [%0], 1;" :: "r"(a) : "memory")
#define MBAR_EXPECT(a,n) asm volatile("mbarrier.arrive.expect_tx.shared.b64 _, [%0], %1;" :: "r"(a), "r"(n) : "memory")
#define BULK_G2S(sa, gp, n, mb) \
    asm volatile("cp.async.bulk.shared::cta.global.mbarrier::complete_tx::bytes [%0], [%1], %2, [%3];" \
        :: "r"(sa), "l"(gp), "r"(n), "r"(mb) : "memory")

#define LDTM32(r, a) \
    asm volatile( \
        "tcgen05.ld.sync.aligned.32x32b.x32.b32 " \
        "{%0, %1, %2, %3, %4, %5, %6, %7, " \
        " %8, %9, %10, %11, %12, %13, %14, %15, " \
        " %16, %17, %18, %19, %20, %21, %22, %23, " \
        " %24, %25, %26, %27, %28, %29, %30, %31}, [%32];" \
        : "=r"((r)[0]),  "=r"((r)[1]),  "=r"((r)[2]),  "=r"((r)[3]), \
          "=r"((r)[4]),  "=r"((r)[5]),  "=r"((r)[6]),  "=r"((r)[7]), \
          "=r"((r)[8]),  "=r"((r)[9]),  "=r"((r)[10]), "=r"((r)[11]), \
          "=r"((r)[12]), "=r"((r)[13]), "=r"((r)[14]), "=r"((r)[15]), \
          "=r"((r)[16]), "=r"((r)[17]), "=r"((r)[18]), "=r"((r)[19]), \
          "=r"((r)[20]), "=r"((r)[21]), "=r"((r)[22]), "=r"((r)[23]), \
          "=r"((r)[24]), "=r"((r)[25]), "=r"((r)[26]), "=r"((r)[27]), \
          "=r"((r)[28]), "=r"((r)[29]), "=r"((r)[30]), "=r"((r)[31]) \
        : "r"(a))

#define LDTM16(r, a) \
    asm volatile( \
        "tcgen05.ld.sync.aligned.32x32b.x16.b32 " \
        "{%0, %1, %2, %3, %4, %5, %6, %7, " \
        " %8, %9, %10, %11, %12, %13, %14, %15}, [%16];" \
        : "=r"((r)[0]),  "=r"((r)[1]),  "=r"((r)[2]),  "=r"((r)[3]), \
          "=r"((r)[4]),  "=r"((r)[5]),  "=r"((r)[6]),  "=r"((r)[7]), \
          "=r"((r)[8]),  "=r"((r)[9]),  "=r"((r)[10]), "=r"((r)[11]), \
          "=r"((r)[12]), "=r"((r)[13]), "=r"((r)[14]), "=r"((r)[15]) \
        : "r"(a))

#define STTM32(a, r) \
    asm volatile( \
        "tcgen05.st.sync.aligned.32x32b.x32.b32 [%0], " \
        "{%1, %2, %3, %4, %5, %6, %7, %8, " \
        " %9, %10, %11, %12, %13, %14, %15, %16, " \
        " %17, %18, %19, %20, %21, %22, %23, %24, " \
        " %25, %26, %27, %28, %29, %30, %31, %32};" \
        :: "r"(a), \
           "r"((r)[0]),  "r"((r)[1]),  "r"((r)[2]),  "r"((r)[3]), \
           "r"((r)[4]),  "r"((r)[5]),  "r"((r)[6]),  "r"((r)[7]), \
           "r"((r)[8]),  "r"((r)[9]),  "r"((r)[10]), "r"((r)[11]), \
           "r"((r)[12]), "r"((r)[13]), "r"((r)[14]), "r"((r)[15]), \
           "r"((r)[16]), "r"((r)[17]), "r"((r)[18]), "r"((r)[19]), \
           "r"((r)[20]), "r"((r)[21]), "r"((r)[22]), "r"((r)[23]), \
           "r"((r)[24]), "r"((r)[25]), "r"((r)[26]), "r"((r)[27]), \
           "r"((r)[28]), "r"((r)[29]), "r"((r)[30]), "r"((r)[31]) \
        : "memory")

#define STTM16(a, r) \
    asm volatile( \
        "tcgen05.st.sync.aligned.32x32b.x16.b32 [%0], " \
        "{%1, %2, %3, %4, %5, %6, %7, %8, " \
        " %9, %10, %11, %12, %13, %14, %15, %16};" \
        :: "r"(a), \
           "r"((r)[0]),  "r"((r)[1]),  "r"((r)[2]),  "r"((r)[3]), \
           "r"((r)[4]),  "r"((r)[5]),  "r"((r)[6]),  "r"((r)[7]), \
           "r"((r)[8]),  "r"((r)[9]),  "r"((r)[10]), "r"((r)[11]), \
           "r"((r)[12]), "r"((r)[13]), "r"((r)[14]), "r"((r)[15]) \
        : "memory")
#endif  // HAS_TC

// ---------------- prep kernels ----------------
__global__ void weights_swz_kernel(const float* __restrict__ Wx,
                                   const float* __restrict__ Wg,
                                   const float* __restrict__ Wo){
    int i = blockIdx.x*blockDim.x + threadIdx.x;
    if (i >= DIM*DIM) return;
    int f = i / DIM, k = i % DIM;
    const float* W = (blockIdx.y == 0) ? Wx : (blockIdx.y == 1) ? Wg : Wo;
    uint32_t v = cvt_tf32(W[i]);
    int ch = k >> 5;
    char* dst = (char*)&g_Wsw[blockIdx.y][0] + (size_t)ch*B_CH_BYTES + loc_off(f, k & 31);
    *(uint32_t*)dst = v;
}

__global__ void compute_MT_kernel(const float* __restrict__ Wk,
                                  const float* __restrict__ Wv,
                                  const float* __restrict__ dmask){
    __shared__ float As[16][17], Bs[16][17];
    int e = blockIdx.x*16 + threadIdx.x;   // 0..239
    float acc = 0.f;
    for (int d0 = 0; d0 < DIM; d0 += 16){
        As[threadIdx.y][threadIdx.x] = Wv[(d0 + threadIdx.y)*DIM + blockIdx.y*16 + threadIdx.x];
        Bs[threadIdx.y][threadIdx.x] = Wk[(d0 + threadIdx.y)*DIM + e];
        __syncthreads();
        #pragma unroll
        for (int dd = 0; dd < 16; dd++)
            acc += As[dd][threadIdx.y] * Bs[dd][threadIdx.x];
        __syncthreads();
    }
    int f = blockIdx.y*16 + threadIdx.y;
    float decay = dmask[SEQ];
    uint32_t v = cvt_tf32(acc * decay);
    int ch = e >> 5;
    char* dst = (char*)g_MTsw + (size_t)ch*B_CH_BYTES + loc_off(f, e & 31);
    *(uint32_t*)dst = v;
}

__global__ void xsw_kernel(const float* __restrict__ x){
    int i = blockIdx.x*blockDim.x + threadIdx.x;
    if (i >= NROW*60) return;
    int r = i / 60, q = i % 60;
    int k = q*4, ch = k >> 5, kl = k & 31;
    float4 v = *(const float4*)(x + (size_t)r*DIM + k);
    uint4 o = make_uint4(cvt_tf32(v.x), cvt_tf32(v.y), cvt_tf32(v.z), cvt_tf32(v.w));
    char* dst = (char*)g_xsw + ((size_t)(r >> 7)*NCHUNK + ch)*A_CH_BYTES + loc_off(r & 127, kl);
    *(uint4*)dst = o;
}

__global__ void cumsum_kernel(const float* __restrict__ x){
    int idx = blockIdx.x*blockDim.x + threadIdx.x;
    if (idx >= NB*DIM) return;
    int b = idx / DIM, d = idx % DIM;
    const float* xp = x    + (size_t)b*SEQ*DIM + d;
    float*       cp = g_Xc + (size_t)b*SEQ*DIM + d;
    float acc = 0.f;
    for (int s = 0; s < SEQ; s += 8){
        float v[8];
        #pragma unroll
        for (int i = 0; i < 8; i++) v[i] = xp[(size_t)(s + i)*DIM];
        #pragma unroll
        for (int i = 0; i < 8; i++){ acc += v[i]; cp[(size_t)(s + i)*DIM] = acc; }
    }
}

// ---------------- K1: diag (persistent, MT resident) ----------------
#define DM    1024u
#define DM_BYTES (NCHUNK*B_CH_BYTES)   // 245760 -- too big; stream MT chunks double-buffered instead
#define DA0   1024u
#define DA1   17408u
#define DM0   33792u
#define DM1   64512u
#define DXC   95232u
#define DG_SMEM 218112u

__global__ void __launch_bounds__(THREADS, 1) __cluster_dims__(1, 1, 1)
diag_tc(const float* __restrict__ x){
#if HAS_TC
    extern __shared__ char smem[];
    uint32_t sb = smem_u32(smem);
    const int tid = threadIdx.x;
    const int wid = tid >> 5, lane = tid & 31;
    const uint32_t FUL0 = sb + 8,  FUL1 = sb + 16;
    const uint32_t FRE0 = sb + 24, FRE1 = sb + 32;
    const uint32_t DONE = sb + 40, XCB = sb + 48;
    const uint32_t abuf[2] = { sb + DA0, sb + DA1 };
    const uint32_t mbuf[2] = { sb + DM0, sb + DM1 };

    if (wid == 0){ TC_ALLOC(sb + 0, 512); TC_RELINQ(); }
    if (tid == 0){ MBAR_INIT(FUL0); MBAR_INIT(FUL1); MBAR_INIT(FRE0); MBAR_INIT(FRE1); MBAR_INIT(DONE); MBAR_INIT(XCB); }
    __syncthreads();
    uint32_t tmem;
    asm volatile("ld.shared.b32 %0, [%1];" : "=r"(tmem) : "r"(sb + 0));

    int isE = 0;
    if (wid == 0) isE = elect_one();
    const uint64_t mg = __cvta_generic_to_global(g_MTsw);

    uint32_t pf0 = 0, pf1 = 0, pr0 = 0, pr1 = 0, pd = 0, pxc = 0;

    for (int t = blockIdx.x; t < NTILES; t += gridDim.x){
        const int row0 = t * MTILE;
        if (isE){
            const uint64_t xg  = __cvta_generic_to_global(g_xsw) + (size_t)t*NCHUNK*A_CH_BYTES;
            const uint64_t xcg = __cvta_generic_to_global(g_Xc) + (size_t)row0*DIM*4;
            MBAR_EXPECT(XCB, XC_BYTES);
            BULK_G2S(sb + DXC, xcg, XC_BYTES, XCB);
            #pragma unroll
            for (int ch = 0; ch < NCHUNK; ch++){
                int p = ch & 1;
                uint32_t FUL = p ? FUL1 : FUL0, FRE = p ? FRE1 : FRE0;
                if (ch >= 2){
                    if (p){ mbar_wait(FRE, pr1); pr1 ^= 1; } else { mbar_wait(FRE, pr0); pr0 ^= 1; }
                }
                MBAR_EXPECT(FUL, A_CH_BYTES + B_CH_BYTES);
                BULK_G2S(abuf[p], xg + (size_t)ch*A_CH_BYTES, A_CH_BYTES, FUL);
                BULK_G2S(mbuf[p], mg + (size_t)ch*B_CH_BYTES, B_CH_BYTES, FUL);
                if (p){ mbar_wait(FUL, pf1); pf1 ^= 1; } else { mbar_wait(FUL, pf0); pf0 ^= 1; }
                uint64_t ad = sdesc(abuf[p]), bd = sdesc(mbuf[p]);
                int nks = (ch == NCHUNK-1) ? 2 : 4;
                for (int ks = 0; ks < nks; ks++)
                    mma_tf32(tmem, ad + ks*2, bd + ks*2, IDESC, (ch | ks) ? 1u : 0u);
                TC_COMMIT(FRE);
            }
            mbar_wait(FRE0, pr0); pr0 ^= 1;
            mbar_wait(FRE1, pr1); pr1 ^= 1;
            TC_COMMIT(DONE);
        }
        mbar_wait(DONE, pd); pd ^= 1;
        mbar_wait(XCB, pxc); pxc ^= 1;
        TC_FENCE_AFTER();

        if (wid < 4){
            int rl = wid*32 + lane;
            int row = row0 + rl;
            const float* xcs = (const float*)(smem + DXC) + (size_t)rl*DIM;
            uint32_t woff = (uint32_t)wid << 21;
            float acc = 0.f;
            for (int c0 = 0; c0 < 240; c0 += 32){
                uint32_t pr[32];
                if (c0 < 224){
                    LDTM32(pr, tmem + c0 + woff);
                    TC_WAIT_LD();
                    #pragma unroll
                    for (int j = 0; j < 8; j++){
                        float4 c4 = *(const float4*)(xcs + c0 + j*4);
                        acc += __uint_as_float(pr[j*4+0])*c4.x + __uint_as_float(pr[j*4+1])*c4.y
                             + __uint_as_float(pr[j*4+2])*c4.z + __uint_as_float(pr[j*4+3])*c4.w;
                    }
                } else {
                    LDTM16(pr, tmem + c0 + woff);
                    TC_WAIT_LD();
                    #pragma unroll
                    for (int j = 0; j < 4; j++){
                        float4 c4 = *(const float4*)(xcs + c0 + j*4);
                        acc += __uint_as_float(pr[j*4+0])*c4.x + __uint_as_float(pr[j*4+1])*c4.y
                             + __uint_as_float(pr[j*4+2])*c4.z + __uint_as_float(pr[j*4+3])*c4.w;
                    }
                }
            }
            int b = row >> 10, s = row & (SEQ - 1);
            g_diagT[(size_t)s*DIM + b] = acc;
            TC_FENCE_BEFORE();
        }
        __syncthreads();
    }
    if (wid == 0) TC_DEALLOC(tmem, 512);
#else
    for (int t = blockIdx.x; t < NTILES; t += gridDim.x){
        const int tid = threadIdx.x;
        const int row0 = t * MTILE;
        __shared__ float red[THREADS];
        int r = tid >> 1, half = tid & 1;
        int row = row0 + r;
        float acc = 0.f;
        for (int f = half*120; f < half*120 + 120; f++){
            float p = 0.f;
            for (int e = 0; e < DIM; e++){
                int ch = e >> 5;
                const char* mp = (const char*)g_MTsw + (size_t)ch*B_CH_BYTES + loc_off(f, e & 31);
                p += x[(size_t)row*DIM + e] * (*(const float*)mp);
            }
            acc += p * g_Xc[(size_t)row*DIM + f];
        }
        red[tid] = acc;
        __syncthreads();
        if (half == 0){
            int b = row >> 10, s = row & (SEQ - 1);
            g_diagT[(size_t)s*DIM + b] = red[tid] + red[tid + 1];
        }
        __syncthreads();
    }
#endif
}

// ---------------- K2: fused final (persistent; Y in TMEM; TS-mode GEMM2) ----
#define FA0   1024u
#define FA1   17408u
#define FX0   33792u
#define FX1   64512u
#define FG0   95232u
#define FG1   125952u
#define FO0   156672u
#define FO1   187392u
#define FN_SMEM 218112u

__global__ void __launch_bounds__(THREADS, 1) __cluster_dims__(1, 1, 1)
final_tc(const float* __restrict__ x,  const float* __restrict__ Wx,
         const float* __restrict__ Wg, const float* __restrict__ Wo,
         const float* __restrict__ bo, float* __restrict__ out){
#if HAS_TC
    extern __shared__ char smem[];
    uint32_t sb = smem_u32(smem);
    const int tid = threadIdx.x;
    const int wid = tid >> 5, lane = tid & 31;
    const uint32_t FUL0 = sb + 8,   FUL1 = sb + 16;
    const uint32_t FRE0 = sb + 24,  FRE1 = sb + 32;
    const uint32_t FUL2 = sb + 40,  FUL3 = sb + 48;
    const uint32_t FRE2 = sb + 56,  FRE3 = sb + 64;
    const uint32_t DONE1 = sb + 72, DONE2 = sb + 80;
    const uint32_t abuf[2] = { sb + FA0, sb + FA1 };
    const uint32_t xbuf[2] = { sb + FX0, sb + FX1 };
    const uint32_t gbuf[2] = { sb + FG0, sb + FG1 };
    const uint32_t obuf[2] = { sb + FO0, sb + FO1 };

    if (wid == 0){ TC_ALLOC(sb + 0, 512); TC_RELINQ(); }
    if (tid == 0){
        MBAR_INIT(FUL0); MBAR_INIT(FUL1); MBAR_INIT(FRE0); MBAR_INIT(FRE1);
        MBAR_INIT(FUL2); MBAR_INIT(FUL3); MBAR_INIT(FRE2); MBAR_INIT(FRE3);
        MBAR_INIT(DONE1); MBAR_INIT(DONE2);
    }
    __syncthreads();
    uint32_t tmem;
    asm volatile("ld.shared.b32 %0, [%1];" : "=r"(tmem) : "r"(sb + 0));

    int isE = 0;
    if (wid == 0) isE = elect_one();

    const uint64_t wxg = __cvta_generic_to_global(&g_Wsw[0][0]);
    const uint64_t wgg = __cvta_generic_to_global(&g_Wsw[1][0]);
    const uint64_t wog = __cvta_generic_to_global(&g_Wsw[2][0]);

    uint32_t pf0=0, pf1=0, pr0=0, pr1=0;
    uint32_t pf2=0, pf3=0, pr2=0, pr3=0;
    uint32_t pd1=0, pd2=0;

    for (int t = blockIdx.x; t < NTILES; t += gridDim.x){
        const int row0 = t * MTILE;
        const uint64_t xg = __cvta_generic_to_global(g_xsw) + (size_t)t*NCHUNK*A_CH_BYTES;

        // ---- GEMM1 (SS): D_xk @ tmem+0, D_g @ tmem+256 ----
        if (isE){
            #pragma unroll
            for (int ch = 0; ch < NCHUNK; ch++){
                int p = ch & 1;
                uint32_t FUL = p ? FUL1 : FUL0, FRE = p ? FRE1 : FRE0;
                if (ch >= 2){
                    if (p){ mbar_wait(FRE, pr1); pr1 ^= 1; } else { mbar_wait(FRE, pr0); pr0 ^= 1; }
                }
                MBAR_EXPECT(FUL, A_CH_BYTES + 2*B_CH_BYTES);
                BULK_G2S(abuf[p], xg  + (size_t)ch*A_CH_BYTES, A_CH_BYTES, FUL);
                BULK_G2S(xbuf[p], wxg + (size_t)ch*B_CH_BYTES, B_CH_BYTES, FUL);
                BULK_G2S(gbuf[p], wgg + (size_t)ch*B_CH_BYTES, B_CH_BYTES, FUL);
                if (p){ mbar_wait(FUL, pf1); pf1 ^= 1; } else { mbar_wait(FUL, pf0); pf0 ^= 1; }
                uint64_t ad = sdesc(abuf[p]), bx = sdesc(xbuf[p]), bg = sdesc(gbuf[p]);
                int nks = (ch == NCHUNK-1) ? 2 : 4;
                for (int ks = 0; ks < nks; ks++){
                    uint32_t en = (ch | ks) ? 1u : 0u;
                    mma_tf32(tmem + 0,   ad + ks*2, bx + ks*2, IDESC, en);
                    mma_tf32(tmem + 256, ad + ks*2, bg + ks*2, IDESC, en);
                }
                TC_COMMIT(FRE);
            }
            mbar_wait(FRE0, pr0); pr0 ^= 1;
            mbar_wait(FRE1, pr1); pr1 ^= 1;
            TC_COMMIT(DONE1);
            // prefetch Wo chunks 0,1 (overlaps epilogue 1)
            MBAR_EXPECT(FUL2, B_CH_BYTES);
            BULK_G2S(obuf[0], wog, B_CH_BYTES, FUL2);
            MBAR_EXPECT(FUL3, B_CH_BYTES);
            BULK_G2S(obuf[1], wog + B_CH_BYTES, B_CH_BYTES, FUL3);
        }
        mbar_wait(DONE1, pd1); pd1 ^= 1;
        TC_FENCE_AFTER();

        // ---- epilogue 1: y = xk * sigmoid(g) * diagT[s, c] -> TMEM Y @ tmem+0
        if (wid < 4){
            int rl = wid*32 + lane;
            int row = row0 + rl;
            int s = row & (SEQ - 1);
            const float* dgr = g_diagT + (size_t)s*DIM;
            uint32_t woff = (uint32_t)wid << 21;
            for (int c0 = 0; c0 < 240; c0 += 32){
                if (c0 < 224){
                    uint32_t xr[32], gr[32], yr[32];
                    LDTM32(xr, tmem + 0   + c0 + woff);
                    LDTM32(gr, tmem + 256 + c0 + woff);
                    TC_WAIT_LD();
                    #pragma unroll
                    for (int j = 0; j < 8; j++){
                        float4 dv = *(const float4*)(dgr + c0 + j*4);
                        yr[j*4+0] = cvt_tf32(__uint_as_float(xr[j*4+0]) * sigf(__uint_as_float(gr[j*4+0])) * dv.x);
                        yr[j*4+1] = cvt_tf32(__uint_as_float(xr[j*4+1]) * sigf(__uint_as_float(gr[j*4+1])) * dv.y);
                        yr[j*4+2] = cvt_tf32(__uint_as_float(xr[j*4+2]) * sigf(__uint_as_float(gr[j*4+2])) * dv.z);
                        yr[j*4+3] = cvt_tf32(__uint_as_float(xr[j*4+3]) * sigf(__uint_as_float(gr[j*4+3])) * dv.w);
                    }
                    STTM32(tmem + 0 + c0 + woff, yr);
                } else {
                    uint32_t xr[16], gr[16], yr[16];
                    LDTM16(xr, tmem + 0   + c0 + woff);
                    LDTM16(gr, tmem + 256 + c0 + woff);
                    TC_WAIT_LD();
                    #pragma unroll
                    for (int j = 0; j < 4; j++){
                        float4 dv = *(const float4*)(dgr + c0 + j*4);
                        yr[j*4+0] = cvt_tf32(__uint_as_float(xr[j*4+0]) * sigf(__uint_as_float(gr[j*4+0])) * dv.x);
                        yr[j*4+1] = cvt_tf32(__uint_as_float(xr[j*4+1]) * sigf(__uint_as_float(gr[j*4+1])) * dv.y);
                        yr[j*4+2] = cvt_tf32(__uint_as_float(xr[j*4+2]) * sigf(__uint_as_float(gr[j*4+2])) * dv.z);
                        yr[j*4+3] = cvt_tf32(__uint_as_float(xr[j*4+3]) * sigf(__uint_as_float(gr[j*4+3])) * dv.w);
                    }
                    STTM16(tmem + 0 + c0 + woff, yr);
                }
            }
            TC_WAIT_ST();
            TC_FENCE_BEFORE();
        }
        __syncthreads();

        // ---- GEMM2 (TS): D_o @ tmem+256, A = Y in TMEM, B = Wo chunks ----
        if (isE){
            TC_FENCE_AFTER();
            #pragma unroll
            for (int ch = 0; ch < NCHUNK; ch++){
                int p = ch & 1;
                uint32_t FUL = p ? FUL3 : FUL2, FRE = p ? FRE3 : FRE2;
                if (ch >= 2){
                    if (p){ mbar_wait(FRE, pr3); pr3 ^= 1; } else { mbar_wait(FRE, pr2); pr2 ^= 1; }
                    MBAR_EXPECT(FUL, B_CH_BYTES);
                    BULK_G2S(obuf[p], wog + (size_t)ch*B_CH_BYTES, B_CH_BYTES, FUL);
                }
                if (p){ mbar_wait(FUL, pf3); pf3 ^= 1; } else { mbar_wait(FUL, pf2); pf2 ^= 1; }
                uint64_t wd = sdesc(obuf[p]);
                int nks = (ch == NCHUNK-1) ? 2 : 4;
                for (int ks = 0; ks < nks; ks++){
                    int gks = ch*4 + ks;
                    mma_tf32_ts(tmem + 256, tmem + 0 + gks*8, wd + ks*2, IDESC, (ch | ks) ? 1u : 0u);
                }
                TC_COMMIT(FRE);
            }
            mbar_wait(FRE2, pr2); pr2 ^= 1;
            mbar_wait(FRE3, pr3); pr3 ^= 1;
            TC_COMMIT(DONE2);
        }
        mbar_wait(DONE2, pd2); pd2 ^= 1;
        TC_FENCE_AFTER();

        // ---- epilogue 2: + bias -> direct STG (per-lane row, contiguous) ----
        if (wid < 4){
            int rl = wid*32 + lane;
            float* orow = out + (size_t)(row0 + rl)*DIM;
            uint32_t woff = (uint32_t)wid << 21;
            for (int c0 = 0; c0 < 240; c0 += 32){
                uint32_t orr[32];
                if (c0 < 224){
                    LDTM32(orr, tmem + 256 + c0 + woff);
                    TC_WAIT_LD();
                    #pragma unroll
                    for (int j = 0; j < 8; j++){
                        float4 bv = *(const float4*)(bo + c0 + j*4);
                        *(float4*)(orow + c0 + j*4) =
                            make_float4(__uint_as_float(orr[j*4+0]) + bv.x,
                                        __uint_as_float(orr[j*4+1]) + bv.y,
                                        __uint_as_float(orr[j*4+2]) + bv.z,
                                        __uint_as_float(orr[j*4+3]) + bv.w);
                    }
                } else {
                    LDTM16(orr, tmem + 256 + c0 + woff);
                    TC_WAIT_LD();
                    #pragma unroll
                    for (int j = 0; j < 4; j++){
                        float4 bv = *(const float4*)(bo + c0 + j*4);
                        *(float4*)(orow + c0 + j*4) =
                            make_float4(__uint_as_float(orr[j*4+0]) + bv.x,
                                        __uint_as_float(orr[j*4+1]) + bv.y,
                                        __uint_as_float(orr[j*4+2]) + bv.z,
                                        __uint_as_float(orr[j*4+3]) + bv.w);
                    }
                }
            }
            TC_FENCE_BEFORE();
        }
        __syncthreads();
    }
    if (wid == 0) TC_DEALLOC(tmem, 512);
#else
    extern __shared__ char smem[];
    float* ys = (float*)(smem + 1024);
    const int tid = threadIdx.x;
    for (int t = blockIdx.x; t < NTILES; t += gridDim.x){
        const int row0 = t * MTILE;
        for (int idx = tid; idx < MTILE*DIM; idx += THREADS){
            int r = idx / DIM, c = idx % DIM;
            int row = row0 + r;
            const float* xr = x + (size_t)row*DIM;
            float xk = 0.f, gp = 0.f;
            for (int e = 0; e < DIM; e++){
                float xe = xr[e];
                xk += xe * Wx[(size_t)c*DIM + e];
                gp += xe * Wg[(size_t)c*DIM + e];
            }
            int s = row & (SEQ - 1);
            ys[(size_t)r*DIM + c] = xk * sigf(gp) * g_diagT[(size_t)s*DIM + c];
        }
        __syncthreads();
        for (int idx = tid; idx < MTILE*DIM; idx += THREADS){
            int r = idx / DIM, c = idx % DIM;
            float acc = bo[c];
            const float* yr = ys + (size_t)r*DIM;
            for (int d = 0; d < DIM; d++) acc += yr[d] * Wo[(size_t)c*DIM + d];
            out[((size_t)(row0 + r))*DIM + c] = acc;
        }
        __syncthreads();
    }
#endif
}

// ---------------- launch ----------------
extern "C" void kernel_launch(void* const* d_in, const int* in_sizes, int n_in,
                              void* d_out, int out_size){
    const float* x     = (const float*)d_in[0];
    const float* Wx    = (const float*)d_in[1];
    const float* Wk    = (const float*)d_in[2];
    const float* Wv    = (const float*)d_in[3];
    const float* Wg    = (const float*)d_in[4];
    const float* Wo    = (const float*)d_in[5];
    const float* bo    = (const float*)d_in[6];
    const float* dmask = (const float*)d_in[7];
    float* out = (float*)d_out;
    (void)in_sizes; (void)n_in; (void)out_size;

    cudaFuncSetAttribute(diag_tc,  cudaFuncAttributeMaxDynamicSharedMemorySize, DG_SMEM);
    cudaFuncSetAttribute(final_tc, cudaFuncAttributeMaxDynamicSharedMemorySize, FN_SMEM);

    weights_swz_kernel<<<dim3((DIM*DIM + 255)/256, 3), 256>>>(Wx, Wg, Wo);
    compute_MT_kernel<<<dim3(15, 15), dim3(16, 16)>>>(Wk, Wv, dmask);
    cumsum_kernel<<<(NB*DIM + 255)/256, 256>>>(x);
    xsw_kernel<<<(NROW*60 + 255)/256, 256>>>(x);
    diag_tc<<<PGRID, THREADS, DG_SMEM>>>(x);
    final_tc<<<PGRID, THREADS, FN_SMEM>>>(x, Wx, Wg, Wo, bo, out);
}

// round 8
// speedup vs baseline: 1.1606x; 1.1606x over previous
#include <cuda_runtime.h>
#include <math.h>
#include <stdint.h>

#define DIM    240
#define SEQ    1024
#define NB     240
#define NROW   (NB*SEQ)      // 245760
#define MTILE  128
#define NTILES (NROW/MTILE)  // 1920
#define NCHUNK 8
#define DTH    160           // diag: warps 0-3 epi, warp 4 producer
#define FTH    288           // final: warps 0-7 epi, warp 8 producer
#define PGRID  152

#define A_CH_BYTES  16384u   // 128 rows x 128B
#define B_CH_BYTES  30720u   // 240 rows x 128B

// idesc: dtype=f32(1<<4), atype=tf32(2<<7), btype=tf32(2<<10), N=240(30<<17), M=128(8<<24)
#define IDESC ((1u<<4)|(2u<<7)|(2u<<10)|(30u<<17)|(8u<<24))

#if !defined(__CUDA_ARCH__) || defined(__CUDA_ARCH_FEAT_SM103_ALL) || defined(__CUDA_ARCH_FEAT_SM100_ALL) || defined(__CUDA_ARCH_FEAT_SM101_ALL)
#define HAS_TC 1
#else
#define HAS_TC 0
#endif

// ---------------- device scratch ----------------
__device__ __align__(1024) float g_Wsw[3][NCHUNK*7680];   // Wx,Wg,Wo swizzled tf32 chunks
__device__ __align__(1024) float g_MTsw[NCHUNK*7680];     // MT swizzled tf32 chunks
__device__ __align__(1024) float g_xsw[(size_t)NROW*256]; // x tiles swizzled tf32
__device__ __align__(1024) float g_Xc [(size_t)NROW*DIM]; // cumsum of x over s
__device__ __align__(1024) float g_diagT[SEQ*DIM];        // diagT[s*240 + b]

// ---------------- helpers ----------------
__device__ __forceinline__ uint32_t smem_u32(const void* p){
    uint32_t a;
    asm("{ .reg .u64 t; cvta.to.shared.u64 t, %1; cvt.u32.u64 %0, t; }" : "=r"(a) : "l"(p));
    return a;
}
__device__ __forceinline__ float sigf(float v){
    float t = -1.4426950408889634f * v;
    float e; asm("ex2.approx.f32 %0, %1;" : "=f"(e) : "f"(t));
    float r; asm("rcp.approx.f32 %0, %1;" : "=f"(r) : "f"(1.f + e));
    return r;
}
__device__ __forceinline__ uint32_t cvt_tf32(float v){
    uint32_t r; asm("cvt.rna.tf32.f32 %0, %1;" : "=r"(r) : "f"(v)); return r;
}
__device__ __forceinline__ uint32_t swz(uint32_t off){ return off ^ ((off >> 3) & 0x70); }
__device__ __forceinline__ uint32_t loc_off(int r, int kl){
    return swz(((uint32_t)(r >> 3) << 10) + ((uint32_t)(r & 7) << 7) + ((uint32_t)kl << 2));
}

#if HAS_TC
__device__ __forceinline__ uint32_t elect_one(){
    uint32_t p;
    asm volatile("{ .reg .pred p; elect.sync _|p, 0xFFFFFFFF; selp.b32 %0, 1, 0, p; }" : "=r"(p));
    return p;
}
__device__ __forceinline__ uint64_t sdesc(uint32_t addr){
    return ((uint64_t)2 << 61) | ((uint64_t)1 << 46) | ((uint64_t)64 << 32)
         | ((uint64_t)1 << 16) | ((uint64_t)(addr >> 4) & 0x3FFF);
}
__device__ __forceinline__ void mma_tf32(uint32_t d, uint64_t a, uint64_t b, uint32_t id, uint32_t en){
    asm volatile(
        "{\n\t.reg .pred p;\n\tsetp.ne.u32 p, %5, 0;\n\t"
        "tcgen05.mma.cta_group::1.kind::tf32 [%0], %1, %2, %3, {%4, %4, %4, %4}, p;\n\t}"
        :: "r"(d), "l"(a), "l"(b), "r"(id), "r"(0u), "r"(en) : "memory");
}
__device__ __forceinline__ void mma_tf32_ts(uint32_t d, uint32_t a, uint64_t b, uint32_t id, uint32_t en){
    asm volatile(
        "{\n\t.reg .pred p;\n\tsetp.ne.u32 p, %5, 0;\n\t"
        "tcgen05.mma.cta_group::1.kind::tf32 [%0], [%1], %2, %3, {%4, %4, %4, %4}, p;\n\t}"
        :: "r"(d), "r"(a), "l"(b), "r"(id), "r"(0u), "r"(en) : "memory");
}
__device__ __forceinline__ void mbar_wait(uint32_t mbar, uint32_t phase){
    asm volatile(
        "{\n\t.reg .pred P;\n\t"
        "W%=:\n\t"
        "mbarrier.try_wait.parity.acquire.cta.shared::cta.b64 P, [%0], %1, 0x989680;\n\t"
        "@P bra.uni D%=;\n\t"
        "bra.uni W%=;\n\t"
        "D%=:\n\t}"
        :: "r"(mbar), "r"(phase) : "memory");
}
#define TC_ALLOC(sa, n)  asm volatile("tcgen05.alloc.cta_group::1.sync.aligned.shared::cta.b32 [%0], %1;" :: "r"(sa), "r"(n) : "memory")
#define TC_RELINQ()      asm volatile("tcgen05.relinquish_alloc_permit.cta_group::1.sync.aligned;")
#define TC_DEALLOC(t, n) asm volatile("tcgen05.dealloc.cta_group::1.sync.aligned.b32 %0, %1;" :: "r"(t), "r"(n))
#define TC_COMMIT(mb)    asm volatile("tcgen05.commit.cta_group::1.mbarrier::arrive::one.shared::cluster.b64 [%0];" :: "r"(mb) : "memory")
#define TC_WAIT_LD()     asm volatile("tcgen05.wait::ld.sync.aligned;" ::: "memory")
#define TC_WAIT_ST()     asm volatile("tcgen05.wait::st.sync.aligned;" ::: "memory")
#define TC_FENCE_AFTER()  asm volatile("tcgen05.fence::after_thread_sync;" ::: "memory")
#define TC_FENCE_BEFORE() asm volatile("tcgen05.fence::before_thread_sync;" ::: "memory")
#define MBAR_INIT(a, c)  asm volatile("mbarrier.init.shared.b64 [%0], %1;" :: "r"(a), "r"(c) : "memory")
#define MBAR_ARRIVE(a)   asm volatile("mbarrier.arrive.shared.b64 _, [%0];" :: "r"(a) : "memory")
#define MBAR_EXPECT(a,n) asm volatile("mbarrier.arrive.expect_tx.shared.b64 _, [%0], %1;" :: "r"(a), "r"(n) : "memory")
#define BULK_G2S(sa, gp, n, mb) \
    asm volatile("cp.async.bulk.shared::cta.global.mbarrier::complete_tx::bytes [%0], [%1], %2, [%3];" \
        :: "r"(sa), "l"(gp), "r"(n), "r"(mb) : "memory")

#define LDTM32(r, a) \
    asm volatile( \
        "tcgen05.ld.sync.aligned.32x32b.x32.b32 " \
        "{%0, %1, %2, %3, %4, %5, %6, %7, " \
        " %8, %9, %10, %11, %12, %13, %14, %15, " \
        " %16, %17, %18, %19, %20, %21, %22, %23, " \
        " %24, %25, %26, %27, %28, %29, %30, %31}, [%32];" \
        : "=r"((r)[0]),  "=r"((r)[1]),  "=r"((r)[2]),  "=r"((r)[3]), \
          "=r"((r)[4]),  "=r"((r)[5]),  "=r"((r)[6]),  "=r"((r)[7]), \
          "=r"((r)[8]),  "=r"((r)[9]),  "=r"((r)[10]), "=r"((r)[11]), \
          "=r"((r)[12]), "=r"((r)[13]), "=r"((r)[14]), "=r"((r)[15]), \
          "=r"((r)[16]), "=r"((r)[17]), "=r"((r)[18]), "=r"((r)[19]), \
          "=r"((r)[20]), "=r"((r)[21]), "=r"((r)[22]), "=r"((r)[23]), \
          "=r"((r)[24]), "=r"((r)[25]), "=r"((r)[26]), "=r"((r)[27]), \
          "=r"((r)[28]), "=r"((r)[29]), "=r"((r)[30]), "=r"((r)[31]) \
        : "r"(a))

#define LDTM16(r, a) \
    asm volatile( \
        "tcgen05.ld.sync.aligned.32x32b.x16.b32 " \
        "{%0, %1, %2, %3, %4, %5, %6, %7, " \
        " %8, %9, %10, %11, %12, %13, %14, %15}, [%16];" \
        : "=r"((r)[0]),  "=r"((r)[1]),  "=r"((r)[2]),  "=r"((r)[3]), \
          "=r"((r)[4]),  "=r"((r)[5]),  "=r"((r)[6]),  "=r"((r)[7]), \
          "=r"((r)[8]),  "=r"((r)[9]),  "=r"((r)[10]), "=r"((r)[11]), \
          "=r"((r)[12]), "=r"((r)[13]), "=r"((r)[14]), "=r"((r)[15]) \
        : "r"(a))

#define STTM32(a, r) \
    asm volatile( \
        "tcgen05.st.sync.aligned.32x32b.x32.b32 [%0], " \
        "{%1, %2, %3, %4, %5, %6, %7, %8, " \
        " %9, %10, %11, %12, %13, %14, %15, %16, " \
        " %17, %18, %19, %20, %21, %22, %23, %24, " \
        " %25, %26, %27, %28, %29, %30, %31, %32};" \
        :: "r"(a), \
           "r"((r)[0]),  "r"((r)[1]),  "r"((r)[2]),  "r"((r)[3]), \
           "r"((r)[4]),  "r"((r)[5]),  "r"((r)[6]),  "r"((r)[7]), \
           "r"((r)[8]),  "r"((r)[9]),  "r"((r)[10]), "r"((r)[11]), \
           "r"((r)[12]), "r"((r)[13]), "r"((r)[14]), "r"((r)[15]), \
           "r"((r)[16]), "r"((r)[17]), "r"((r)[18]), "r"((r)[19]), \
           "r"((r)[20]), "r"((r)[21]), "r"((r)[22]), "r"((r)[23]), \
           "r"((r)[24]), "r"((r)[25]), "r"((r)[26]), "r"((r)[27]), \
           "r"((r)[28]), "r"((r)[29]), "r"((r)[30]), "r"((r)[31]) \
        : "memory")

#define STTM16(a, r) \
    asm volatile( \
        "tcgen05.st.sync.aligned.32x32b.x16.b32 [%0], " \
        "{%1, %2, %3, %4, %5, %6, %7, %8, " \
        " %9, %10, %11, %12, %13, %14, %15, %16};" \
        :: "r"(a), \
           "r"((r)[0]),  "r"((r)[1]),  "r"((r)[2]),  "r"((r)[3]), \
           "r"((r)[4]),  "r"((r)[5]),  "r"((r)[6]),  "r"((r)[7]), \
           "r"((r)[8]),  "r"((r)[9]),  "r"((r)[10]), "r"((r)[11]), \
           "r"((r)[12]), "r"((r)[13]), "r"((r)[14]), "r"((r)[15]) \
        : "memory")
#endif  // HAS_TC

// ---------------- prep kernels ----------------
__global__ void weights_swz_kernel(const float* __restrict__ Wx,
                                   const float* __restrict__ Wg,
                                   const float* __restrict__ Wo){
    int i = blockIdx.x*blockDim.x + threadIdx.x;
    if (i >= DIM*DIM) return;
    int f = i / DIM, k = i % DIM;
    const float* W = (blockIdx.y == 0) ? Wx : (blockIdx.y == 1) ? Wg : Wo;
    uint32_t v = cvt_tf32(W[i]);
    int ch = k >> 5;
    char* dst = (char*)&g_Wsw[blockIdx.y][0] + (size_t)ch*B_CH_BYTES + loc_off(f, k & 31);
    *(uint32_t*)dst = v;
}

__global__ void compute_MT_kernel(const float* __restrict__ Wk,
                                  const float* __restrict__ Wv,
                                  const float* __restrict__ dmask){
    __shared__ float As[16][17], Bs[16][17];
    int e = blockIdx.x*16 + threadIdx.x;   // 0..239
    float acc = 0.f;
    for (int d0 = 0; d0 < DIM; d0 += 16){
        As[threadIdx.y][threadIdx.x] = Wv[(d0 + threadIdx.y)*DIM + blockIdx.y*16 + threadIdx.x];
        Bs[threadIdx.y][threadIdx.x] = Wk[(d0 + threadIdx.y)*DIM + e];
        __syncthreads();
        #pragma unroll
        for (int dd = 0; dd < 16; dd++)
            acc += As[dd][threadIdx.y] * Bs[dd][threadIdx.x];
        __syncthreads();
    }
    int f = blockIdx.y*16 + threadIdx.y;
    float decay = dmask[SEQ];              // decay_mask[1][0] == 0.9
    uint32_t v = cvt_tf32(acc * decay);
    int ch = e >> 5;
    char* dst = (char*)g_MTsw + (size_t)ch*B_CH_BYTES + loc_off(f, e & 31);
    *(uint32_t*)dst = v;
}

// fused: cumsum of x over s  AND  tf32-swizzled x tile images (single x read)
__global__ void xprep_kernel(const float* __restrict__ x){
    int idx = blockIdx.x*blockDim.x + threadIdx.x;
    if (idx >= NB*DIM) return;
    int b = idx / DIM, d = idx % DIM;
    int ch = d >> 5, kl = d & 31;
    const float* xp = x    + (size_t)b*SEQ*DIM + d;
    float*       cp = g_Xc + (size_t)b*SEQ*DIM + d;
    char* xb = (char*)g_xsw + ((size_t)b*NCHUNK*8 + ch)*A_CH_BYTES;   // tile = b*8 + (s>>7)
    float acc = 0.f;
    for (int s = 0; s < SEQ; s += 8){
        float v[8];
        #pragma unroll
        for (int i = 0; i < 8; i++) v[i] = xp[(size_t)(s + i)*DIM];
        #pragma unroll
        for (int i = 0; i < 8; i++){
            acc += v[i];
            cp[(size_t)(s + i)*DIM] = acc;
            int row = s + i;
            char* dst = xb + (size_t)(row >> 7)*NCHUNK*A_CH_BYTES + loc_off(row & 127, kl);
            *(uint32_t*)dst = cvt_tf32(v[i]);
        }
    }
}

// ---------------- K1: diag (persistent, TMEM double-buffered, run-ahead) ----
#define DA0   1024u
#define DA1   17408u
#define DM0   33792u
#define DM1   64512u
#define DG_SMEM 95232u

__global__ void __launch_bounds__(DTH, 1) __cluster_dims__(1, 1, 1)
diag_tc(const float* __restrict__ x){
#if HAS_TC
    extern __shared__ char smem[];
    uint32_t sb = smem_u32(smem);
    const int tid = threadIdx.x;
    const int wid = tid >> 5, lane = tid & 31;
    const uint32_t FUL0 = sb + 8,  FUL1 = sb + 16;
    const uint32_t FRE0 = sb + 24, FRE1 = sb + 32;
    const uint32_t DONE0 = sb + 40, DONE1 = sb + 48;
    const uint32_t EPI0 = sb + 56,  EPI1 = sb + 64;
    const uint32_t abuf[2] = { sb + DA0, sb + DA1 };
    const uint32_t mbuf[2] = { sb + DM0, sb + DM1 };

    if (wid == 0){ TC_ALLOC(sb + 0, 512); TC_RELINQ(); }
    if (tid == 0){
        MBAR_INIT(FUL0, 1); MBAR_INIT(FUL1, 1); MBAR_INIT(FRE0, 1); MBAR_INIT(FRE1, 1);
        MBAR_INIT(DONE0, 1); MBAR_INIT(DONE1, 1); MBAR_INIT(EPI0, 4); MBAR_INIT(EPI1, 4);
    }
    __syncthreads();
    uint32_t tmem;
    asm volatile("ld.shared.b32 %0, [%1];" : "=r"(tmem) : "r"(sb + 0));

    if (wid == 4){
        // ---------------- producer: GEMM one tile ahead ----------------
        if (elect_one()){
            const uint64_t mg = __cvta_generic_to_global(g_MTsw);
            uint32_t pf0=0, pf1=0, pr0=0, pr1=0, pe0=0, pe1=0;
            int i = 0;
            for (int t = blockIdx.x; t < NTILES; t += gridDim.x, i++){
                int slot = i & 1;
                uint32_t dtm = tmem + (slot ? 256u : 0u);
                const uint64_t xg = __cvta_generic_to_global(g_xsw) + (size_t)t*NCHUNK*A_CH_BYTES;
                #pragma unroll
                for (int ch = 0; ch < NCHUNK; ch++){
                    int p = ch & 1;
                    uint32_t FUL = p ? FUL1 : FUL0, FRE = p ? FRE1 : FRE0;
                    if (ch >= 2){
                        if (p){ mbar_wait(FRE, pr1); pr1 ^= 1; } else { mbar_wait(FRE, pr0); pr0 ^= 1; }
                    }
                    MBAR_EXPECT(FUL, A_CH_BYTES + B_CH_BYTES);
                    BULK_G2S(abuf[p], xg + (size_t)ch*A_CH_BYTES, A_CH_BYTES, FUL);
                    BULK_G2S(mbuf[p], mg + (size_t)ch*B_CH_BYTES, B_CH_BYTES, FUL);
                    if (p){ mbar_wait(FUL, pf1); pf1 ^= 1; } else { mbar_wait(FUL, pf0); pf0 ^= 1; }
                    if (ch == 0){
                        if (i >= 2){
                            if (slot){ mbar_wait(EPI1, pe1); pe1 ^= 1; }
                            else     { mbar_wait(EPI0, pe0); pe0 ^= 1; }
                        }
                        TC_FENCE_AFTER();
                    }
                    uint64_t ad = sdesc(abuf[p]), bd = sdesc(mbuf[p]);
                    int nks = (ch == NCHUNK-1) ? 2 : 4;
                    for (int ks = 0; ks < nks; ks++)
                        mma_tf32(dtm, ad + ks*2, bd + ks*2, IDESC, (ch | ks) ? 1u : 0u);
                    TC_COMMIT(FRE);
                }
                mbar_wait(FRE0, pr0); pr0 ^= 1;
                mbar_wait(FRE1, pr1); pr1 ^= 1;
                TC_COMMIT(slot ? DONE1 : DONE0);
            }
        }
    } else if (wid < 4){
        // ---------------- consumers: epilogue (dot with Xc) ----------------
        uint32_t pd0 = 0, pd1 = 0;
        uint32_t woff = (uint32_t)wid << 21;
        int i = 0;
        for (int t = blockIdx.x; t < NTILES; t += gridDim.x, i++){
            int slot = i & 1;
            uint32_t dtm = tmem + (slot ? 256u : 0u);
            int row0 = t * MTILE;
            if (slot){ mbar_wait(DONE1, pd1); pd1 ^= 1; }
            else     { mbar_wait(DONE0, pd0); pd0 ^= 1; }
            TC_FENCE_AFTER();

            int rl = wid*32 + lane;
            int row = row0 + rl;
            const float* xcs = g_Xc + (size_t)row*DIM;
            float acc = 0.f;
            for (int c0 = 0; c0 < 240; c0 += 32){
                uint32_t pr[32];
                if (c0 < 224){
                    LDTM32(pr, dtm + c0 + woff);
                    TC_WAIT_LD();
                    #pragma unroll
                    for (int j = 0; j < 8; j++){
                        float4 c4 = *(const float4*)(xcs + c0 + j*4);
                        acc += __uint_as_float(pr[j*4+0])*c4.x + __uint_as_float(pr[j*4+1])*c4.y
                             + __uint_as_float(pr[j*4+2])*c4.z + __uint_as_float(pr[j*4+3])*c4.w;
                    }
                } else {
                    LDTM16(pr, dtm + c0 + woff);
                    TC_WAIT_LD();
                    #pragma unroll
                    for (int j = 0; j < 4; j++){
                        float4 c4 = *(const float4*)(xcs + c0 + j*4);
                        acc += __uint_as_float(pr[j*4+0])*c4.x + __uint_as_float(pr[j*4+1])*c4.y
                             + __uint_as_float(pr[j*4+2])*c4.z + __uint_as_float(pr[j*4+3])*c4.w;
                    }
                }
            }
            int b = row >> 10, s = row & (SEQ - 1);
            g_diagT[(size_t)s*DIM + b] = acc;
            TC_FENCE_BEFORE();
            if (lane == 0) MBAR_ARRIVE(slot ? EPI1 : EPI0);
        }
    }
    __syncthreads();
    if (wid == 0) TC_DEALLOC(tmem, 512);
#else
    const int tid = threadIdx.x;
    for (int t = blockIdx.x; t < NTILES; t += gridDim.x){
        const int row0 = t * MTILE;
        for (int r = tid; r < MTILE; r += blockDim.x){
            int row = row0 + r;
            float acc = 0.f;
            for (int f = 0; f < DIM; f++){
                float p = 0.f;
                for (int e = 0; e < DIM; e++){
                    int ch = e >> 5;
                    const char* mp = (const char*)g_MTsw + (size_t)ch*B_CH_BYTES + loc_off(f, e & 31);
                    p += x[(size_t)row*DIM + e] * (*(const float*)mp);
                }
                acc += p * g_Xc[(size_t)row*DIM + f];
            }
            int b = row >> 10, s = row & (SEQ - 1);
            g_diagT[(size_t)s*DIM + b] = acc;
        }
    }
#endif
}

// ---------------- K2: fused final (9 warps; mbarrier-only pipeline) --------
#define FA0   1024u
#define FA1   17408u
#define FX0   33792u
#define FX1   64512u
#define FG0   95232u
#define FG1   125952u
#define FO0   156672u
#define FO1   187392u
#define FN_SMEM 218112u

__global__ void __launch_bounds__(FTH, 1) __cluster_dims__(1, 1, 1)
final_tc(const float* __restrict__ x,  const float* __restrict__ Wx,
         const float* __restrict__ Wg, const float* __restrict__ Wo,
         const float* __restrict__ bo, float* __restrict__ out){
#if HAS_TC
    extern __shared__ char smem[];
    uint32_t sb = smem_u32(smem);
    const int tid = threadIdx.x;
    const int wid = tid >> 5, lane = tid & 31;
    const uint32_t FUL0 = sb + 8,   FUL1 = sb + 16;
    const uint32_t FRE0 = sb + 24,  FRE1 = sb + 32;
    const uint32_t FUL2 = sb + 40,  FUL3 = sb + 48;
    const uint32_t FRE2 = sb + 56,  FRE3 = sb + 64;
    const uint32_t DONE1 = sb + 72, DONE2 = sb + 80;
    const uint32_t EPIA = sb + 88,  EPIB = sb + 96;
    const uint32_t abuf[2] = { sb + FA0, sb + FA1 };
    const uint32_t xbuf[2] = { sb + FX0, sb + FX1 };
    const uint32_t gbuf[2] = { sb + FG0, sb + FG1 };
    const uint32_t obuf[2] = { sb + FO0, sb + FO1 };

    if (wid == 0){ TC_ALLOC(sb + 0, 512); TC_RELINQ(); }
    if (tid == 0){
        MBAR_INIT(FUL0, 1); MBAR_INIT(FUL1, 1); MBAR_INIT(FRE0, 1); MBAR_INIT(FRE1, 1);
        MBAR_INIT(FUL2, 1); MBAR_INIT(FUL3, 1); MBAR_INIT(FRE2, 1); MBAR_INIT(FRE3, 1);
        MBAR_INIT(DONE1, 1); MBAR_INIT(DONE2, 1); MBAR_INIT(EPIA, 8); MBAR_INIT(EPIB, 8);
    }
    __syncthreads();
    uint32_t tmem;
    asm volatile("ld.shared.b32 %0, [%1];" : "=r"(tmem) : "r"(sb + 0));

    if (wid == 8){
        // ---------------- producer: all staging + all MMAs ----------------
        if (elect_one()){
            const uint64_t wxg = __cvta_generic_to_global(&g_Wsw[0][0]);
            const uint64_t wgg = __cvta_generic_to_global(&g_Wsw[1][0]);
            const uint64_t wog = __cvta_generic_to_global(&g_Wsw[2][0]);
            uint32_t pf0=0, pf1=0, pr0=0, pr1=0;
            uint32_t pf2=0, pf3=0, pr2=0, pr3=0;
            uint32_t pea=0, peb=0;
            int i = 0;
            for (int t = blockIdx.x; t < NTILES; t += gridDim.x, i++){
                const uint64_t xg = __cvta_generic_to_global(g_xsw) + (size_t)t*NCHUNK*A_CH_BYTES;
                // ---- GEMM1 (SS): xk @ tmem+0, g @ tmem+256 ----
                #pragma unroll
                for (int ch = 0; ch < NCHUNK; ch++){
                    int p = ch & 1;
                    uint32_t FUL = p ? FUL1 : FUL0, FRE = p ? FRE1 : FRE0;
                    if (ch >= 2){
                        if (p){ mbar_wait(FRE, pr1); pr1 ^= 1; } else { mbar_wait(FRE, pr0); pr0 ^= 1; }
                    }
                    MBAR_EXPECT(FUL, A_CH_BYTES + 2*B_CH_BYTES);
                    BULK_G2S(abuf[p], xg  + (size_t)ch*A_CH_BYTES, A_CH_BYTES, FUL);
                    BULK_G2S(xbuf[p], wxg + (size_t)ch*B_CH_BYTES, B_CH_BYTES, FUL);
                    BULK_G2S(gbuf[p], wgg + (size_t)ch*B_CH_BYTES, B_CH_BYTES, FUL);
                    if (p){ mbar_wait(FUL, pf1); pf1 ^= 1; } else { mbar_wait(FUL, pf0); pf0 ^= 1; }
                    if (ch == 0){
                        if (i >= 1){ mbar_wait(EPIB, peb); peb ^= 1; }   // epi2 of prev tile done
                        TC_FENCE_AFTER();
                    }
                    uint64_t ad = sdesc(abuf[p]), bx = sdesc(xbuf[p]), bg = sdesc(gbuf[p]);
                    int nks = (ch == NCHUNK-1) ? 2 : 4;
                    for (int ks = 0; ks < nks; ks++){
                        uint32_t en = (ch | ks) ? 1u : 0u;
                        mma_tf32(tmem + 0,   ad + ks*2, bx + ks*2, IDESC, en);
                        mma_tf32(tmem + 256, ad + ks*2, bg + ks*2, IDESC, en);
                    }
                    TC_COMMIT(FRE);
                }
                mbar_wait(FRE0, pr0); pr0 ^= 1;
                mbar_wait(FRE1, pr1); pr1 ^= 1;
                TC_COMMIT(DONE1);
                // prefetch Wo chunks 0,1 (overlaps epi1)
                MBAR_EXPECT(FUL2, B_CH_BYTES);
                BULK_G2S(obuf[0], wog, B_CH_BYTES, FUL2);
                MBAR_EXPECT(FUL3, B_CH_BYTES);
                BULK_G2S(obuf[1], wog + B_CH_BYTES, B_CH_BYTES, FUL3);
                // ---- GEMM2 (TS): out @ tmem+256, A = Y in TMEM ----
                #pragma unroll
                for (int ch = 0; ch < NCHUNK; ch++){
                    int p = ch & 1;
                    uint32_t FUL = p ? FUL3 : FUL2, FRE = p ? FRE3 : FRE2;
                    if (ch >= 2){
                        if (p){ mbar_wait(FRE, pr3); pr3 ^= 1; } else { mbar_wait(FRE, pr2); pr2 ^= 1; }
                        MBAR_EXPECT(FUL, B_CH_BYTES);
                        BULK_G2S(obuf[p], wog + (size_t)ch*B_CH_BYTES, B_CH_BYTES, FUL);
                    }
                    if (p){ mbar_wait(FUL, pf3); pf3 ^= 1; } else { mbar_wait(FUL, pf2); pf2 ^= 1; }
                    if (ch == 0){
                        mbar_wait(EPIA, pea); pea ^= 1;                 // Y ready
                        TC_FENCE_AFTER();
                    }
                    uint64_t wd = sdesc(obuf[p]);
                    int nks = (ch == NCHUNK-1) ? 2 : 4;
                    for (int ks = 0; ks < nks; ks++){
                        int gks = ch*4 + ks;
                        mma_tf32_ts(tmem + 256, tmem + 0 + gks*8, wd + ks*2, IDESC, (ch | ks) ? 1u : 0u);
                    }
                    TC_COMMIT(FRE);
                }
                mbar_wait(FRE2, pr2); pr2 ^= 1;
                mbar_wait(FRE3, pr3); pr3 ^= 1;
                TC_COMMIT(DONE2);
            }
        }
    } else {
        // ---------------- epilogue warps 0-7 ----------------
        const int grp = wid >> 2;        // 0: cols 0..127, 1: cols 128..239
        const int subp = wid & 3;
        const uint32_t woff = (uint32_t)subp << 21;
        const int rl = subp*32 + lane;
        uint32_t pd1 = 0, pd2 = 0;
        for (int t = blockIdx.x; t < NTILES; t += gridDim.x){
            const int row0 = t * MTILE;
            // ---- epi1: y = xk * sigmoid(g) * diagT[s, c] -> TMEM tmem+0 ----
            mbar_wait(DONE1, pd1); pd1 ^= 1;
            TC_FENCE_AFTER();
            {
                int row = row0 + rl;
                int s = row & (SEQ - 1);
                const float* dgr = g_diagT + (size_t)s*DIM;
                int cbeg = grp ? 128 : 0, cend = grp ? 224 : 128;
                for (int c0 = cbeg; c0 < cend; c0 += 32){
                    uint32_t xr[32], gr[32], yr[32];
                    LDTM32(xr, tmem + 0   + c0 + woff);
                    LDTM32(gr, tmem + 256 + c0 + woff);
                    TC_WAIT_LD();
                    #pragma unroll
                    for (int j = 0; j < 8; j++){
                        float4 dv = *(const float4*)(dgr + c0 + j*4);
                        yr[j*4+0] = cvt_tf32(__uint_as_float(xr[j*4+0]) * sigf(__uint_as_float(gr[j*4+0])) * dv.x);
                        yr[j*4+1] = cvt_tf32(__uint_as_float(xr[j*4+1]) * sigf(__uint_as_float(gr[j*4+1])) * dv.y);
                        yr[j*4+2] = cvt_tf32(__uint_as_float(xr[j*4+2]) * sigf(__uint_as_float(gr[j*4+2])) * dv.z);
                        yr[j*4+3] = cvt_tf32(__uint_as_float(xr[j*4+3]) * sigf(__uint_as_float(gr[j*4+3])) * dv.w);
                    }
                    STTM32(tmem + 0 + c0 + woff, yr);
                }
                if (grp == 1){   // cols 224..239
                    uint32_t xr[16], gr[16], yr[16];
                    LDTM16(xr, tmem + 0   + 224 + woff);
                    LDTM16(gr, tmem + 256 + 224 + woff);
                    TC_WAIT_LD();
                    #pragma unroll
                    for (int j = 0; j < 4; j++){
                        float4 dv = *(const float4*)(dgr + 224 + j*4);
                        yr[j*4+0] = cvt_tf32(__uint_as_float(xr[j*4+0]) * sigf(__uint_as_float(gr[j*4+0])) * dv.x);
                        yr[j*4+1] = cvt_tf32(__uint_as_float(xr[j*4+1]) * sigf(__uint_as_float(gr[j*4+1])) * dv.y);
                        yr[j*4+2] = cvt_tf32(__uint_as_float(xr[j*4+2]) * sigf(__uint_as_float(gr[j*4+2])) * dv.z);
                        yr[j*4+3] = cvt_tf32(__uint_as_float(xr[j*4+3]) * sigf(__uint_as_float(gr[j*4+3])) * dv.w);
                    }
                    STTM16(tmem + 0 + 224 + woff, yr);
                }
                TC_WAIT_ST();
                TC_FENCE_BEFORE();
            }
            if (lane == 0) MBAR_ARRIVE(EPIA);
            // ---- epi2: out = D + bias -> GMEM ----
            mbar_wait(DONE2, pd2); pd2 ^= 1;
            TC_FENCE_AFTER();
            {
                float* orow = out + (size_t)(row0 + rl)*DIM;
                int cbeg = grp ? 128 : 0, cend = grp ? 224 : 128;
                for (int c0 = cbeg; c0 < cend; c0 += 32){
                    uint32_t orr[32];
                    LDTM32(orr, tmem + 256 + c0 + woff);
                    TC_WAIT_LD();
                    #pragma unroll
                    for (int j = 0; j < 8; j++){
                        float4 bv = *(const float4*)(bo + c0 + j*4);
                        *(float4*)(orow + c0 + j*4) =
                            make_float4(__uint_as_float(orr[j*4+0]) + bv.x,
                                        __uint_as_float(orr[j*4+1]) + bv.y,
                                        __uint_as_float(orr[j*4+2]) + bv.z,
                                        __uint_as_float(orr[j*4+3]) + bv.w);
                    }
                }
                if (grp == 1){
                    uint32_t orr[16];
                    LDTM16(orr, tmem + 256 + 224 + woff);
                    TC_WAIT_LD();
                    #pragma unroll
                    for (int j = 0; j < 4; j++){
                        float4 bv = *(const float4*)(bo + 224 + j*4);
                        *(float4*)(orow + 224 + j*4) =
                            make_float4(__uint_as_float(orr[j*4+0]) + bv.x,
                                        __uint_as_float(orr[j*4+1]) + bv.y,
                                        __uint_as_float(orr[j*4+2]) + bv.z,
                                        __uint_as_float(orr[j*4+3]) + bv.w);
                    }
                }
                TC_FENCE_BEFORE();
            }
            if (lane == 0) MBAR_ARRIVE(EPIB);
        }
    }
    __syncthreads();
    if (wid == 0) TC_DEALLOC(tmem, 512);
#else
    extern __shared__ char smem[];
    float* ys = (float*)(smem + 1024);
    const int tid = threadIdx.x;
    for (int t = blockIdx.x; t < NTILES; t += gridDim.x){
        const int row0 = t * MTILE;
        for (int idx = tid; idx < MTILE*DIM; idx += blockDim.x){
            int r = idx / DIM, c = idx % DIM;
            int row = row0 + r;
            const float* xr = x + (size_t)row*DIM;
            float xk = 0.f, gp = 0.f;
            for (int e = 0; e < DIM; e++){
                float xe = xr[e];
                xk += xe * Wx[(size_t)c*DIM + e];
                gp += xe * Wg[(size_t)c*DIM + e];
            }
            int s = row & (SEQ - 1);
            ys[(size_t)r*DIM + c] = xk * sigf(gp) * g_diagT[(size_t)s*DIM + c];
        }
        __syncthreads();
        for (int idx = tid; idx < MTILE*DIM; idx += blockDim.x){
            int r = idx / DIM, c = idx % DIM;
            float acc = bo[c];
            const float* yr = ys + (size_t)r*DIM;
            for (int d = 0; d < DIM; d++) acc += yr[d] * Wo[(size_t)c*DIM + d];
            out[((size_t)(row0 + r))*DIM + c] = acc;
        }
        __syncthreads();
    }
#endif
}

// ---------------- launch ----------------
extern "C" void kernel_launch(void* const* d_in, const int* in_sizes, int n_in,
                              void* d_out, int out_size){
    const float* x     = (const float*)d_in[0];
    const float* Wx    = (const float*)d_in[1];
    const float* Wk    = (const float*)d_in[2];
    const float* Wv    = (const float*)d_in[3];
    const float* Wg    = (const float*)d_in[4];
    const float* Wo    = (const float*)d_in[5];
    const float* bo    = (const float*)d_in[6];
    const float* dmask = (const float*)d_in[7];
    float* out = (float*)d_out;
    (void)in_sizes; (void)n_in; (void)out_size;

    cudaFuncSetAttribute(diag_tc,  cudaFuncAttributeMaxDynamicSharedMemorySize, DG_SMEM);
    cudaFuncSetAttribute(final_tc, cudaFuncAttributeMaxDynamicSharedMemorySize, FN_SMEM);

    weights_swz_kernel<<<dim3((DIM*DIM + 255)/256, 3), 256>>>(Wx, Wg, Wo);
    compute_MT_kernel<<<dim3(15, 15), dim3(16, 16)>>>(Wk, Wv, dmask);
    xprep_kernel<<<(NB*DIM + 255)/256, 256>>>(x);
    diag_tc<<<PGRID, DTH, DG_SMEM>>>(x);
    final_tc<<<PGRID, FTH, FN_SMEM>>>(x, Wx, Wg, Wo, bo, out);
}